// round 12
// baseline (speedup 1.0000x reference)
#include <cuda_runtime.h>
#include <cuda_fp16.h>
#include <cstdint>
#include <math.h>

#define SEQ 2048
#define H 16
#define KVH 8
#define D 128
#define HID 2048
#define INTERM 8192
#define SCALE 0.08838834764831845f

// ---------------- scratch (device globals) ----------------
__device__ float  g_qkv[SEQ * 4096];            // q|k|v fp32 from GEMM
__device__ __half g_xnh[SEQ * HID];
__device__ __half g_qh[SEQ * 2048], g_ql[SEQ * 2048];
__device__ __half g_kh[SEQ * 1024], g_vh[SEQ * 1024];
__device__ __half g_aoh[SEQ * 2048];
__device__ float  g_hb[SEQ * HID];
__device__ __half g_yh[SEQ * HID];
__device__ __half g_gh[SEQ * INTERM];
// weights fp16
__device__ __half g_wqkvh[4096 * 2048];
__device__ __half g_woh[2048 * 2048];
__device__ __half g_wguh[16384 * 2048];         // gate/up row-interleaved
__device__ __half g_wdh[2048 * 8192];

// ================= helpers =================
__device__ __forceinline__ uint32_t smem_to_u32(const void* p) {
    uint32_t a;
    asm("{ .reg .u64 t; cvta.to.shared.u64 t, %1; cvt.u32.u64 %0, t; }" : "=r"(a) : "l"(p));
    return a;
}
__device__ __forceinline__ uint32_t pack_h2(float a, float b) {
    __half2 h = __floats2half2_rn(a, b);
    return *reinterpret_cast<uint32_t*>(&h);
}
__device__ __forceinline__ void ldsm4(uint32_t* r, uint32_t addr) {
    asm volatile("ldmatrix.sync.aligned.m8n8.x4.shared.b16 {%0,%1,%2,%3}, [%4];"
                 : "=r"(r[0]), "=r"(r[1]), "=r"(r[2]), "=r"(r[3]) : "r"(addr));
}
__device__ __forceinline__ void ldsm4t(uint32_t* r, uint32_t addr) {
    asm volatile("ldmatrix.sync.aligned.m8n8.x4.trans.shared.b16 {%0,%1,%2,%3}, [%4];"
                 : "=r"(r[0]), "=r"(r[1]), "=r"(r[2]), "=r"(r[3]) : "r"(addr));
}
__device__ __forceinline__ void mma16816(float* c, const uint32_t* a, const uint32_t* b) {
    asm volatile(
        "mma.sync.aligned.m16n8k16.row.col.f32.f16.f16.f32 "
        "{%0,%1,%2,%3}, {%4,%5,%6,%7}, {%8,%9}, {%0,%1,%2,%3};"
        : "+f"(c[0]), "+f"(c[1]), "+f"(c[2]), "+f"(c[3])
        : "r"(a[0]), "r"(a[1]), "r"(a[2]), "r"(a[3]), "r"(b[0]), "r"(b[1]));
}
#define CP16(dst, src) \
    asm volatile("cp.async.cg.shared.global [%0], [%1], 16;" :: "r"(dst), "l"(src) : "memory")
#define CPCOMMIT() asm volatile("cp.async.commit_group;" ::: "memory")
#define CPWAIT0()  asm volatile("cp.async.wait_group 0;" ::: "memory")

// =================================================================
// hmma_gemm<SILU>: C = alpha * A[M,K] @ B[N,K]^T (+ add), fp16 both
// sides, single term. R11 skeleton (K chunk 32, 80-B rows, 2-kk
// body) but PAIR-PROCESSED: one __syncthreads + one cp.async wait
// per TWO K-iters. 4 stages of 20480 B (Ah@0, Bh@10240).
// SILU: adjacent (even,odd) output cols are (gate,up) -> silu(g)*u.
// =================================================================
#define STG 20480
#define HM_SMEM (4 * STG)

template <bool SILU>
__global__ void __launch_bounds__(256, 2) hmma_gemm(
    const __half* __restrict__ Ah, const __half* __restrict__ Bh,
    float* __restrict__ C, int ldc,
    const float* __restrict__ add, float alpha, int K,
    __half* __restrict__ HC) {
    extern __shared__ char sm[];
    const int tid = threadIdx.x;
    const int lane = tid & 31, wid = tid >> 5;
    const int wm = wid >> 1, wn = wid & 1;
    const int m0 = blockIdx.y * 128, n0 = blockIdx.x * 128;

    const uint32_t sb = smem_to_u32(sm);
    const uint32_t aoff = sb + (uint32_t)(wm * 32 + (lane & 15)) * 80 + (uint32_t)(lane >> 4) * 16;
    const uint32_t boff = sb + 10240 + (uint32_t)(wn * 64 + (lane & 15)) * 80 + (uint32_t)(lane >> 4) * 16;

    const int r = tid >> 1;
    const uint32_t sA = (uint32_t)r * 80 + (uint32_t)(tid & 1) * 32;
    const char* agh = (const char*)(Ah + (size_t)(m0 + r) * K) + (tid & 1) * 32;
    const char* bgh = (const char*)(Bh + (size_t)(n0 + r) * K) + (tid & 1) * 32;

#define PREFETCH(st, kt) do { \
    const uint32_t _d = sb + (uint32_t)(st) * STG + sA; \
    const size_t _o = (size_t)(kt) * 64; \
    CP16(_d,          agh + _o); CP16(_d + 16,          agh + _o + 16); \
    CP16(_d + 10240,  bgh + _o); CP16(_d + 10240 + 16,  bgh + _o + 16); \
    CPCOMMIT(); \
} while (0)

// one K32 sub-chunk of MMAs on stage `st`
#define COMPUTE32(st) do { \
    const uint32_t _so = (uint32_t)(st) * STG; \
    _Pragma("unroll") \
    for (int kk = 0; kk < 2; kk++) { \
        uint32_t ah[2][4], bh[4][4]; \
        _Pragma("unroll") \
        for (int mt = 0; mt < 2; mt++) \
            ldsm4(ah[mt], aoff + _so + mt * 1280 + kk * 32); \
        _Pragma("unroll") \
        for (int g = 0; g < 4; g++) ldsm4(bh[g], boff + _so + g * 1280 + kk * 32); \
        _Pragma("unroll") \
        for (int mt = 0; mt < 2; mt++) \
            _Pragma("unroll") \
            for (int nt = 0; nt < 8; nt++) { \
                const int g = nt >> 1, o = nt & 1; \
                uint32_t bf[2] = {bh[g][o], bh[g][o + 2]}; \
                mma16816(acc[mt][nt], ah[mt], bf); \
            } \
    } \
} while (0)

    float acc[2][8][4];
#pragma unroll
    for (int i = 0; i < 2; i++)
#pragma unroll
        for (int j = 0; j < 8; j++)
#pragma unroll
            for (int l = 0; l < 4; l++) acc[i][j][l] = 0.f;

    const int np = K >> 6;   // number of K64 pairs; K = 2048 or 8192 -> 32 / 128
    PREFETCH(0, 0);
    PREFETCH(1, 1);

    for (int p = 0; p < np; p++) {
        const int kt = p * 2;
        CPWAIT0();            // both pending groups (kt, kt+1) have landed
        __syncthreads();      // and all warps are done reading the other two stages
        if (p + 1 < np) {
            PREFETCH((kt + 2) & 3, kt + 2);
            PREFETCH((kt + 3) & 3, kt + 3);
        }
        COMPUTE32(kt & 3);
        COMPUTE32((kt + 1) & 3);
    }
    __syncthreads();

    const int rb = m0 + wm * 32 + (lane >> 2);
    const int cb = n0 + wn * 64 + (lane & 3) * 2;
    if (SILU) {
#pragma unroll
        for (int mt = 0; mt < 2; mt++)
#pragma unroll
            for (int nt = 0; nt < 8; nt++) {
                const int r0 = rb + mt * 16;
                const int oc = (cb + nt * 8) >> 1;
                float g0 = acc[mt][nt][0], u0 = acc[mt][nt][1];
                float g1 = acc[mt][nt][2], u1 = acc[mt][nt][3];
                float v0 = g0 / (1.f + __expf(-g0)) * u0;
                float v1 = g1 / (1.f + __expf(-g1)) * u1;
                HC[(size_t)r0 * (ldc >> 1) + oc] = __float2half_rn(v0);
                HC[(size_t)(r0 + 8) * (ldc >> 1) + oc] = __float2half_rn(v1);
            }
    } else {
#pragma unroll
        for (int mt = 0; mt < 2; mt++)
#pragma unroll
            for (int nt = 0; nt < 8; nt++) {
                const int r0 = rb + mt * 16;
                const int c = cb + nt * 8;
                float2 v0 = make_float2(alpha * acc[mt][nt][0], alpha * acc[mt][nt][1]);
                float2 v1 = make_float2(alpha * acc[mt][nt][2], alpha * acc[mt][nt][3]);
                if (add) {
                    float2 d0 = *(const float2*)(add + (size_t)r0 * ldc + c);
                    float2 d1 = *(const float2*)(add + (size_t)(r0 + 8) * ldc + c);
                    v0.x += d0.x; v0.y += d0.y; v1.x += d1.x; v1.y += d1.y;
                }
                *(float2*)(C + (size_t)r0 * ldc + c) = v0;
                *(float2*)(C + (size_t)(r0 + 8) * ldc + c) = v1;
            }
    }
}

// =================================================================
// flash attention: Q split hi/lo fp16, K,V,P single fp16.
// K/V double-buffered cp.async. V via ldmatrix.trans. fp16 out.
// =================================================================
#define FQH 0
#define FQL 34816
#define FKH0 69632
#define FKH1 104448
#define FVH0 139264
#define FVH1 174080
#define FSD0 208896
#define FSD1 209408
#define FL_SMEM 209920

__global__ void __launch_bounds__(256, 1) flash_attn(
    const __half* __restrict__ qh, const __half* __restrict__ ql,
    const __half* __restrict__ kh, const __half* __restrict__ vh,
    const int* __restrict__ sid, __half* __restrict__ aoh) {
    extern __shared__ char sm[];
    const int z = blockIdx.x;
    const int ib = 15 - (z >> 4);
    const int h = z & 15;
    const int kvh = h >> 1;
    const int tid = threadIdx.x, lane = tid & 31, w = tid >> 5;
    const uint32_t sb = smem_to_u32(sm);

    const int r = tid >> 1;
    const uint32_t half_off = (uint32_t)(tid & 1) * 128;
    const int hcol = (tid & 1) * 64;
    const uint32_t dstrow = sb + (uint32_t)r * 272 + half_off;

#define KVLOAD(jb, kdst, vdst) do { \
    const __half* _ks = kh + (size_t)((jb) * 128 + r) * 1024 + kvh * 128 + hcol; \
    const __half* _vs = vh + (size_t)((jb) * 128 + r) * 1024 + kvh * 128 + hcol; \
    _Pragma("unroll") \
    for (int x = 0; x < 8; x++) { \
        CP16(dstrow + (kdst) + x * 16, (const char*)_ks + x * 16); \
        CP16(dstrow + (vdst) + x * 16, (const char*)_vs + x * 16); \
    } \
} while (0)

    {
        const __half* qsh = qh + (size_t)(ib * 128 + r) * 2048 + h * 128 + hcol;
        const __half* qsl = ql + (size_t)(ib * 128 + r) * 2048 + h * 128 + hcol;
#pragma unroll
        for (int x = 0; x < 8; x++) {
            CP16(dstrow + FQH + x * 16, (const char*)qsh + x * 16);
            CP16(dstrow + FQL + x * 16, (const char*)qsl + x * 16);
        }
        KVLOAD(0, FKH0, FVH0);
        CPCOMMIT();
        if (tid < 128) ((int*)(sm + FSD0))[tid] = sid[tid];
    }

    const int r0g = ib * 128 + w * 16 + (lane >> 2);
    const int sid0 = sid[r0g], sid1 = sid[r0g + 8];

    float m0 = -1e30f, m1 = -1e30f, l0 = 0.f, l1 = 0.f;
    float oa[16][4];
#pragma unroll
    for (int i = 0; i < 16; i++)
#pragma unroll
        for (int j = 0; j < 4; j++) oa[i][j] = 0.f;

    const uint32_t arh = sb + FQH + (uint32_t)(w * 16 + (lane & 15)) * 272 + (uint32_t)(lane >> 4) * 16;
    const uint32_t arl = arh + (FQL - FQH);
    const int vg = lane >> 3, vlr = lane & 7;
    const uint32_t vrow_off = (uint32_t)((vg & 1) * 8 + vlr) * 272 + (uint32_t)(vg >> 1) * 16;

    for (int jb = 0; jb <= ib; jb++) {
        const int buf = jb & 1;
        const uint32_t kbase = sb + (buf ? FKH1 : FKH0);
        const uint32_t vbase = sb + (buf ? FVH1 : FVH0);
        const int* sid_sm = (const int*)(sm + (buf ? FSD1 : FSD0));

        CPWAIT0();
        __syncthreads();
        if (jb < ib) {
            if (buf) KVLOAD(jb + 1, FKH0, FVH0); else KVLOAD(jb + 1, FKH1, FVH1);
            CPCOMMIT();
            if (tid < 128) ((int*)(sm + (buf ? FSD0 : FSD1)))[tid] = sid[(jb + 1) * 128 + tid];
        }

        float s[16][4];
#pragma unroll
        for (int i = 0; i < 16; i++)
#pragma unroll
            for (int j = 0; j < 4; j++) s[i][j] = 0.f;

#pragma unroll
        for (int kk = 0; kk < 8; kk++) {
            uint32_t ah[4], al[4];
            ldsm4(ah, arh + kk * 32);
            ldsm4(al, arl + kk * 32);
#pragma unroll
            for (int ng = 0; ng < 8; ng++) {
                uint32_t bh[4];
                ldsm4(bh, kbase + (uint32_t)(ng * 16 + (lane & 15)) * 272
                              + (uint32_t)(lane >> 4) * 16 + kk * 32);
#pragma unroll
                for (int o = 0; o < 2; o++) {
                    uint32_t bf[2] = {bh[o], bh[o + 2]};
                    mma16816(s[ng * 2 + o], ah, bf);
                    mma16816(s[ng * 2 + o], al, bf);
                }
            }
        }

        const int cloc = (lane & 3) * 2;
#pragma unroll
        for (int nt = 0; nt < 16; nt++) {
            const int c0l = nt * 8 + cloc;
            const int sc0 = sid_sm[c0l], sc1 = sid_sm[c0l + 1];
            const int c0gl = jb * 128 + c0l;
            s[nt][0] = (sc0 == sid0 && c0gl <= r0g)         ? s[nt][0] * SCALE : -1e30f;
            s[nt][1] = (sc1 == sid0 && c0gl + 1 <= r0g)     ? s[nt][1] * SCALE : -1e30f;
            s[nt][2] = (sc0 == sid1 && c0gl <= r0g + 8)     ? s[nt][2] * SCALE : -1e30f;
            s[nt][3] = (sc1 == sid1 && c0gl + 1 <= r0g + 8) ? s[nt][3] * SCALE : -1e30f;
        }

        float tm0 = -1e30f, tm1 = -1e30f;
#pragma unroll
        for (int nt = 0; nt < 16; nt++) {
            tm0 = fmaxf(tm0, fmaxf(s[nt][0], s[nt][1]));
            tm1 = fmaxf(tm1, fmaxf(s[nt][2], s[nt][3]));
        }
        tm0 = fmaxf(tm0, __shfl_xor_sync(~0u, tm0, 1));
        tm0 = fmaxf(tm0, __shfl_xor_sync(~0u, tm0, 2));
        tm1 = fmaxf(tm1, __shfl_xor_sync(~0u, tm1, 1));
        tm1 = fmaxf(tm1, __shfl_xor_sync(~0u, tm1, 2));
        const float nm0 = fmaxf(m0, tm0), nm1 = fmaxf(m1, tm1);
        const float cf0 = __expf(m0 - nm0), cf1 = __expf(m1 - nm1);
        m0 = nm0; m1 = nm1;
        float rs0 = 0.f, rs1 = 0.f;
#pragma unroll
        for (int nt = 0; nt < 16; nt++) {
            float p0 = (s[nt][0] > -1e29f) ? __expf(s[nt][0] - nm0) : 0.f;
            float p1 = (s[nt][1] > -1e29f) ? __expf(s[nt][1] - nm0) : 0.f;
            float p2 = (s[nt][2] > -1e29f) ? __expf(s[nt][2] - nm1) : 0.f;
            float p3 = (s[nt][3] > -1e29f) ? __expf(s[nt][3] - nm1) : 0.f;
            s[nt][0] = p0; s[nt][1] = p1; s[nt][2] = p2; s[nt][3] = p3;
            rs0 += p0 + p1; rs1 += p2 + p3;
        }
        l0 = l0 * cf0 + rs0;
        l1 = l1 * cf1 + rs1;
#pragma unroll
        for (int nt = 0; nt < 16; nt++) {
            oa[nt][0] *= cf0; oa[nt][1] *= cf0;
            oa[nt][2] *= cf1; oa[nt][3] *= cf1;
        }

        // ---- O += P @ V (P single fp16) ----
#pragma unroll
        for (int kp = 0; kp < 8; kp++) {
            uint32_t pah[4];
            {
                const float* t0 = s[kp * 2];
                const float* t1 = s[kp * 2 + 1];
                pah[0] = pack_h2(t0[0], t0[1]);
                pah[1] = pack_h2(t0[2], t0[3]);
                pah[2] = pack_h2(t1[0], t1[1]);
                pah[3] = pack_h2(t1[2], t1[3]);
            }
            const uint32_t vk = vbase + (uint32_t)(kp * 16) * 272 + vrow_off;
#pragma unroll
            for (int ng = 0; ng < 8; ng++) {
                uint32_t vb[4];
                ldsm4t(vb, vk + ng * 32);
#pragma unroll
                for (int o = 0; o < 2; o++) {
                    uint32_t bf[2] = {vb[o * 2], vb[o * 2 + 1]};
                    mma16816(oa[ng * 2 + o], pah, bf);
                }
            }
        }
    }

    l0 += __shfl_xor_sync(~0u, l0, 1); l0 += __shfl_xor_sync(~0u, l0, 2);
    l1 += __shfl_xor_sync(~0u, l1, 1); l1 += __shfl_xor_sync(~0u, l1, 2);
    const float i0 = 1.f / l0, i1 = 1.f / l1;
    const int cbase = h * D + (lane & 3) * 2;
    uint32_t* oh0 = (uint32_t*)aoh + (((size_t)r0g * 2048 + cbase) >> 1);
    uint32_t* oh1 = (uint32_t*)aoh + (((size_t)(r0g + 8) * 2048 + cbase) >> 1);
#pragma unroll
    for (int nt = 0; nt < 16; nt++) {
        oh0[nt * 4] = pack_h2(oa[nt][0] * i0, oa[nt][1] * i0);
        oh1[nt * 4] = pack_h2(oa[nt][2] * i1, oa[nt][3] * i1);
    }
}

// ================= elementwise kernels =================
__global__ void split16_v4(const float4* __restrict__ in, uint2* __restrict__ out, int n4) {
    const int stride = gridDim.x * blockDim.x;
    for (int i = blockIdx.x * blockDim.x + threadIdx.x; i < n4; i += stride) {
        float4 a = in[i];
        out[i] = make_uint2(pack_h2(a.x, a.y), pack_h2(a.z, a.w));
    }
}

// interleave wg/wu rows: dst row 2j = wg[j], 2j+1 = wu[j]; float4 granularity
__global__ void interleave16_v4(const float4* __restrict__ wg, const float4* __restrict__ wu,
                                uint2* __restrict__ dst) {
    const int n4 = INTERM * (HID / 4);
    const int stride = gridDim.x * blockDim.x;
    for (int i = blockIdx.x * blockDim.x + threadIdx.x; i < n4; i += stride) {
        int j = i >> 9, cq = i & 511;          // HID/4 = 512
        float4 a = wg[i];
        float4 b = wu[i];
        dst[(size_t)(2 * j) * 512 + cq] = make_uint2(pack_h2(a.x, a.y), pack_h2(a.z, a.w));
        dst[(size_t)(2 * j + 1) * 512 + cq] = make_uint2(pack_h2(b.x, b.y), pack_h2(b.z, b.w));
    }
}

__global__ void rmsnorm16(const float* __restrict__ x, const float* __restrict__ w,
                          __half* __restrict__ oh, int dim) {
    int row = blockIdx.x;
    const float* xr = x + (size_t)row * dim;
    float ss = 0.f;
    for (int i = threadIdx.x; i < dim; i += blockDim.x) { float v = xr[i]; ss += v * v; }
    __shared__ float red[32];
    for (int o = 16; o; o >>= 1) ss += __shfl_xor_sync(~0u, ss, o);
    if ((threadIdx.x & 31) == 0) red[threadIdx.x >> 5] = ss;
    __syncthreads();
    if (threadIdx.x < 32) {
        float v = (threadIdx.x < (blockDim.x >> 5)) ? red[threadIdx.x] : 0.f;
        for (int o = 16; o; o >>= 1) v += __shfl_xor_sync(~0u, v, o);
        if (threadIdx.x == 0) red[0] = v;
    }
    __syncthreads();
    float inv = rsqrtf(red[0] / (float)dim + 1e-6f);
    for (int i = threadIdx.x * 2; i < dim; i += blockDim.x * 2) {
        float v0 = xr[i] * inv * w[i];
        float v1 = xr[i + 1] * inv * w[i + 1];
        ((uint32_t*)oh)[((size_t)row * dim + i) >> 1] = pack_h2(v0, v1);
    }
}

__global__ void rope_split(const float* __restrict__ qkv, const int* __restrict__ pos,
                           __half* __restrict__ qh, __half* __restrict__ ql,
                           __half* __restrict__ kh, __half* __restrict__ vh) {
    int idx = blockIdx.x * blockDim.x + threadIdx.x;
    if (idx >= SEQ * 32 * 64) return;
    int j = idx & 63;
    int slot = (idx >> 6) & 31;
    int srow = idx >> 11;
    const float* base = qkv + (size_t)srow * 4096 + slot * 128;
    float x0 = base[j], x1 = base[j + 64];
    float y0, y1;
    if (slot < 24) {
        float p = (float)pos[srow];
        float invf = __expf(-(float)j * (logf(10000.f) / 64.f));
        float ang = p * invf;
        float c = cosf(ang), sn = sinf(ang);
        y0 = x0 * c - x1 * sn;
        y1 = x1 * c + x0 * sn;
    } else { y0 = x0; y1 = x1; }
    if (slot < 16) {
        size_t o = (size_t)srow * 2048 + slot * 128;
        __half h0 = __float2half_rn(y0), h1 = __float2half_rn(y1);
        qh[o + j] = h0;      qh[o + j + 64] = h1;
        ql[o + j] = __float2half_rn(y0 - __half2float(h0));
        ql[o + j + 64] = __float2half_rn(y1 - __half2float(h1));
    } else if (slot < 24) {
        size_t o = (size_t)srow * 1024 + (slot - 16) * 128;
        kh[o + j] = __float2half_rn(y0);
        kh[o + j + 64] = __float2half_rn(y1);
    } else {
        size_t o = (size_t)srow * 1024 + (slot - 24) * 128;
        vh[o + j] = __float2half_rn(y0);
        vh[o + j + 64] = __float2half_rn(y1);
    }
}

extern "C" void kernel_launch(void* const* d_in, const int* in_sizes, int n_in,
                              void* d_out, int out_size) {
    const float* hs  = (const float*)d_in[0];
    const int*   sid = (const int*)d_in[1];
    const int*   pos = (const int*)d_in[2];
    const float* ln1 = (const float*)d_in[3];
    const float* wq  = (const float*)d_in[4];
    const float* wk  = (const float*)d_in[5];
    const float* wv  = (const float*)d_in[6];
    const float* wo  = (const float*)d_in[7];
    const float* ln2 = (const float*)d_in[8];
    const float* wg  = (const float*)d_in[9];
    const float* wu  = (const float*)d_in[10];
    const float* wd  = (const float*)d_in[11];
    float* out = (float*)d_out;

    float *qkv, *hb;
    __half *xnh, *qh, *ql, *kh, *vh, *aoh, *yh, *gh;
    __half *wqkvh, *woh, *wguh, *wdh;
    cudaGetSymbolAddress((void**)&qkv, g_qkv);
    cudaGetSymbolAddress((void**)&hb,  g_hb);
    cudaGetSymbolAddress((void**)&xnh, g_xnh);
    cudaGetSymbolAddress((void**)&qh,  g_qh);  cudaGetSymbolAddress((void**)&ql, g_ql);
    cudaGetSymbolAddress((void**)&kh,  g_kh);  cudaGetSymbolAddress((void**)&vh, g_vh);
    cudaGetSymbolAddress((void**)&aoh, g_aoh);
    cudaGetSymbolAddress((void**)&yh,  g_yh);
    cudaGetSymbolAddress((void**)&gh,  g_gh);
    cudaGetSymbolAddress((void**)&wqkvh, g_wqkvh);
    cudaGetSymbolAddress((void**)&woh,   g_woh);
    cudaGetSymbolAddress((void**)&wguh,  g_wguh);
    cudaGetSymbolAddress((void**)&wdh,   g_wdh);

    cudaFuncSetAttribute(hmma_gemm<false>, cudaFuncAttributeMaxDynamicSharedMemorySize, HM_SMEM);
    cudaFuncSetAttribute(hmma_gemm<true>,  cudaFuncAttributeMaxDynamicSharedMemorySize, HM_SMEM);
    cudaFuncSetAttribute(flash_attn, cudaFuncAttributeMaxDynamicSharedMemorySize, FL_SMEM);

    // Launch order arranged so ncu (-s 5 -c 1) captures the QKV hmma_gemm (index 5).
    split16_v4<<<1184, 256>>>((const float4*)wq, (uint2*)wqkvh, 2048 * 2048 / 4);                    // 0
    split16_v4<<<1184, 256>>>((const float4*)wk, (uint2*)(wqkvh + 2048 * 2048), 1024 * 2048 / 4);    // 1
    split16_v4<<<1184, 256>>>((const float4*)wv, (uint2*)(wqkvh + 3072 * 2048), 1024 * 2048 / 4);    // 2
    rmsnorm16<<<SEQ, 256>>>(hs, ln1, xnh, HID);                                                      // 3
    split16_v4<<<1184, 256>>>((const float4*)wo, (uint2*)woh, 2048 * 2048 / 4);                      // 4
    hmma_gemm<false><<<dim3(32, 16), 256, HM_SMEM>>>(xnh, wqkvh, qkv, 4096, nullptr, 1.f, HID, nullptr); // 5: QKV
    interleave16_v4<<<2368, 256>>>((const float4*)wg, (const float4*)wu, (uint2*)wguh);              // 6
    split16_v4<<<2368, 256>>>((const float4*)wd, (uint2*)wdh, 2048 * 8192 / 4);                      // 7
    rope_split<<<(SEQ * 32 * 64 + 255) / 256, 256>>>(qkv, pos, qh, ql, kh, vh);                      // 8
    flash_attn<<<256, 256, FL_SMEM>>>(qh, ql, kh, vh, sid, aoh);                                     // 9
    hmma_gemm<false><<<dim3(16, 16), 256, HM_SMEM>>>(aoh, woh, hb, HID, hs, 1.f, 2048, nullptr);     // 10
    rmsnorm16<<<SEQ, 256>>>(hb, ln2, yh, HID);                                                       // 11
    hmma_gemm<true><<<dim3(128, 16), 256, HM_SMEM>>>(yh, wguh, nullptr, 16384, nullptr, 1.f, HID, gh); // 12
    hmma_gemm<false><<<dim3(16, 16), 256, HM_SMEM>>>(gh, wdh, out, HID, hb, 1.f, INTERM, nullptr);   // 13
}

// round 13
// speedup vs baseline: 1.0109x; 1.0109x over previous
#include <cuda_runtime.h>
#include <cuda_fp16.h>
#include <cstdint>
#include <math.h>

#define SEQ 2048
#define H 16
#define KVH 8
#define D 128
#define HID 2048
#define INTERM 8192
#define SCALE 0.08838834764831845f

// ---------------- scratch (device globals) ----------------
__device__ float  g_qkv[SEQ * 4096];
__device__ __half g_xnh[SEQ * HID];
__device__ __half g_qh[SEQ * 2048], g_ql[SEQ * 2048];
__device__ __half g_kh[SEQ * 1024], g_vh[SEQ * 1024];
__device__ __half g_aoh[SEQ * 2048];
__device__ float  g_hb[SEQ * HID];
__device__ __half g_yh[SEQ * HID];
__device__ __half g_gh[SEQ * INTERM];
__device__ __half g_wqkvh[4096 * 2048];
__device__ __half g_woh[2048 * 2048];
__device__ __half g_wguh[16384 * 2048];
__device__ __half g_wdh[2048 * 8192];

// ================= helpers =================
__device__ __forceinline__ uint32_t smem_to_u32(const void* p) {
    uint32_t a;
    asm("{ .reg .u64 t; cvta.to.shared.u64 t, %1; cvt.u32.u64 %0, t; }" : "=r"(a) : "l"(p));
    return a;
}
__device__ __forceinline__ uint32_t pack_h2(float a, float b) {
    __half2 h = __floats2half2_rn(a, b);
    return *reinterpret_cast<uint32_t*>(&h);
}
__device__ __forceinline__ void ldsm4(uint32_t* r, uint32_t addr) {
    asm volatile("ldmatrix.sync.aligned.m8n8.x4.shared.b16 {%0,%1,%2,%3}, [%4];"
                 : "=r"(r[0]), "=r"(r[1]), "=r"(r[2]), "=r"(r[3]) : "r"(addr));
}
__device__ __forceinline__ void ldsm4t(uint32_t* r, uint32_t addr) {
    asm volatile("ldmatrix.sync.aligned.m8n8.x4.trans.shared.b16 {%0,%1,%2,%3}, [%4];"
                 : "=r"(r[0]), "=r"(r[1]), "=r"(r[2]), "=r"(r[3]) : "r"(addr));
}
__device__ __forceinline__ void mma16816(float* c, const uint32_t* a, const uint32_t* b) {
    asm volatile(
        "mma.sync.aligned.m16n8k16.row.col.f32.f16.f16.f32 "
        "{%0,%1,%2,%3}, {%4,%5,%6,%7}, {%8,%9}, {%0,%1,%2,%3};"
        : "+f"(c[0]), "+f"(c[1]), "+f"(c[2]), "+f"(c[3])
        : "r"(a[0]), "r"(a[1]), "r"(a[2]), "r"(a[3]), "r"(b[0]), "r"(b[1]));
}
#define CP16(dst, src) \
    asm volatile("cp.async.cg.shared.global [%0], [%1], 16;" :: "r"(dst), "l"(src) : "memory")
#define CPCOMMIT() asm volatile("cp.async.commit_group;" ::: "memory")
#define CPWAIT0()  asm volatile("cp.async.wait_group 0;" ::: "memory")
#define CPWAIT1()  asm volatile("cp.async.wait_group 1;" ::: "memory")
#define CPWAIT2()  asm volatile("cp.async.wait_group 2;" ::: "memory")

// ================= hmma_gemm (R11 best-measured version) =================
#define STG 20480
#define HM_SMEM (4 * STG)

template <bool SILU>
__global__ void __launch_bounds__(256, 2) hmma_gemm(
    const __half* __restrict__ Ah, const __half* __restrict__ Bh,
    float* __restrict__ C, int ldc,
    const float* __restrict__ add, float alpha, int K,
    __half* __restrict__ HC) {
    extern __shared__ char sm[];
    const int tid = threadIdx.x;
    const int lane = tid & 31, wid = tid >> 5;
    const int wm = wid >> 1, wn = wid & 1;
    const int m0 = blockIdx.y * 128, n0 = blockIdx.x * 128;

    const uint32_t sb = smem_to_u32(sm);
    const uint32_t aoff = sb + (uint32_t)(wm * 32 + (lane & 15)) * 80 + (uint32_t)(lane >> 4) * 16;
    const uint32_t boff = sb + 10240 + (uint32_t)(wn * 64 + (lane & 15)) * 80 + (uint32_t)(lane >> 4) * 16;

    const int r = tid >> 1;
    const uint32_t sA = (uint32_t)r * 80 + (uint32_t)(tid & 1) * 32;
    const char* agh = (const char*)(Ah + (size_t)(m0 + r) * K) + (tid & 1) * 32;
    const char* bgh = (const char*)(Bh + (size_t)(n0 + r) * K) + (tid & 1) * 32;

#define PREFETCH(st, kt) do { \
    const uint32_t _d = sb + (uint32_t)(st) * STG + sA; \
    const size_t _o = (size_t)(kt) * 64; \
    CP16(_d,          agh + _o); CP16(_d + 16,          agh + _o + 16); \
    CP16(_d + 10240,  bgh + _o); CP16(_d + 10240 + 16,  bgh + _o + 16); \
    CPCOMMIT(); \
} while (0)

    float acc[2][8][4];
#pragma unroll
    for (int i = 0; i < 2; i++)
#pragma unroll
        for (int j = 0; j < 8; j++)
#pragma unroll
            for (int l = 0; l < 4; l++) acc[i][j][l] = 0.f;

    const int nk = K >> 5;
    PREFETCH(0, 0);
    PREFETCH(1, 1);
    PREFETCH(2, 2);

    for (int kt = 0; kt < nk; kt++) {
        const int ahead = nk - kt - 1;
        if (ahead >= 2)      CPWAIT2();
        else if (ahead == 1) CPWAIT1();
        else                 CPWAIT0();
        __syncthreads();
        if (kt + 3 < nk) PREFETCH((kt + 3) & 3, kt + 3);
        const uint32_t so = (uint32_t)(kt & 3) * STG;

#pragma unroll
        for (int kk = 0; kk < 2; kk++) {
            uint32_t ah[2][4], bh[4][4];
#pragma unroll
            for (int mt = 0; mt < 2; mt++)
                ldsm4(ah[mt], aoff + so + mt * 1280 + kk * 32);
#pragma unroll
            for (int g = 0; g < 4; g++) ldsm4(bh[g], boff + so + g * 1280 + kk * 32);
#pragma unroll
            for (int mt = 0; mt < 2; mt++)
#pragma unroll
                for (int nt = 0; nt < 8; nt++) {
                    const int g = nt >> 1, o = nt & 1;
                    uint32_t bf[2] = {bh[g][o], bh[g][o + 2]};
                    mma16816(acc[mt][nt], ah[mt], bf);
                }
        }
    }
    __syncthreads();

    const int rb = m0 + wm * 32 + (lane >> 2);
    const int cb = n0 + wn * 64 + (lane & 3) * 2;
    if (SILU) {
#pragma unroll
        for (int mt = 0; mt < 2; mt++)
#pragma unroll
            for (int nt = 0; nt < 8; nt++) {
                const int r0 = rb + mt * 16;
                const int oc = (cb + nt * 8) >> 1;
                float g0 = acc[mt][nt][0], u0 = acc[mt][nt][1];
                float g1 = acc[mt][nt][2], u1 = acc[mt][nt][3];
                float v0 = g0 / (1.f + __expf(-g0)) * u0;
                float v1 = g1 / (1.f + __expf(-g1)) * u1;
                HC[(size_t)r0 * (ldc >> 1) + oc] = __float2half_rn(v0);
                HC[(size_t)(r0 + 8) * (ldc >> 1) + oc] = __float2half_rn(v1);
            }
    } else {
#pragma unroll
        for (int mt = 0; mt < 2; mt++)
#pragma unroll
            for (int nt = 0; nt < 8; nt++) {
                const int r0 = rb + mt * 16;
                const int c = cb + nt * 8;
                float2 v0 = make_float2(alpha * acc[mt][nt][0], alpha * acc[mt][nt][1]);
                float2 v1 = make_float2(alpha * acc[mt][nt][2], alpha * acc[mt][nt][3]);
                if (add) {
                    float2 d0 = *(const float2*)(add + (size_t)r0 * ldc + c);
                    float2 d1 = *(const float2*)(add + (size_t)(r0 + 8) * ldc + c);
                    v0.x += d0.x; v0.y += d0.y; v1.x += d1.x; v1.y += d1.y;
                }
                *(float2*)(C + (size_t)r0 * ldc + c) = v0;
                *(float2*)(C + (size_t)(r0 + 8) * ldc + c) = v1;
            }
    }
}

// ================= flash attention, LPT-paired =================
// grid 128: CTA z handles head (z&15) and q-blocks ib = 15-p and p
// (p = z>>4), giving every CTA exactly 17 block-iters (one wave).
#define FQH 0
#define FQL 34816
#define FKH0 69632
#define FKH1 104448
#define FVH0 139264
#define FVH1 174080
#define FSD0 208896
#define FSD1 209408
#define FL_SMEM 209920

__global__ void __launch_bounds__(256, 1) flash_attn(
    const __half* __restrict__ qh, const __half* __restrict__ ql,
    const __half* __restrict__ kh, const __half* __restrict__ vh,
    const int* __restrict__ sid, __half* __restrict__ aoh) {
    extern __shared__ char sm[];
    const int z = blockIdx.x;
    const int p = z >> 4;
    const int h = z & 15;
    const int kvh = h >> 1;
    const int tid = threadIdx.x, lane = tid & 31, w = tid >> 5;
    const uint32_t sb = smem_to_u32(sm);

    const int r = tid >> 1;
    const uint32_t half_off = (uint32_t)(tid & 1) * 128;
    const int hcol = (tid & 1) * 64;
    const uint32_t dstrow = sb + (uint32_t)r * 272 + half_off;

#define KVLOAD(jb, kdst, vdst) do { \
    const __half* _ks = kh + (size_t)((jb) * 128 + r) * 1024 + kvh * 128 + hcol; \
    const __half* _vs = vh + (size_t)((jb) * 128 + r) * 1024 + kvh * 128 + hcol; \
    _Pragma("unroll") \
    for (int x = 0; x < 8; x++) { \
        CP16(dstrow + (kdst) + x * 16, (const char*)_ks + x * 16); \
        CP16(dstrow + (vdst) + x * 16, (const char*)_vs + x * 16); \
    } \
} while (0)

    const int vg = lane >> 3, vlr = lane & 7;
    const uint32_t vrow_off = (uint32_t)((vg & 1) * 8 + vlr) * 272 + (uint32_t)(vg >> 1) * 16;
    const uint32_t arh = sb + FQH + (uint32_t)(w * 16 + (lane & 15)) * 272 + (uint32_t)(lane >> 4) * 16;
    const uint32_t arl = arh + (FQL - FQH);

    for (int half = 0; half < 2; half++) {
        const int ib = half == 0 ? 15 - p : p;
        __syncthreads();   // previous half's smem reads fully done

        // prologue: Q (hi+lo) + KV(0) + sid(0)
        {
            const __half* qsh = qh + (size_t)(ib * 128 + r) * 2048 + h * 128 + hcol;
            const __half* qsl = ql + (size_t)(ib * 128 + r) * 2048 + h * 128 + hcol;
#pragma unroll
            for (int x = 0; x < 8; x++) {
                CP16(dstrow + FQH + x * 16, (const char*)qsh + x * 16);
                CP16(dstrow + FQL + x * 16, (const char*)qsl + x * 16);
            }
            KVLOAD(0, FKH0, FVH0);
            CPCOMMIT();
            if (tid < 128) ((int*)(sm + FSD0))[tid] = sid[tid];
        }

        const int r0g = ib * 128 + w * 16 + (lane >> 2);
        const int sid0 = sid[r0g], sid1 = sid[r0g + 8];

        float m0 = -1e30f, m1 = -1e30f, l0 = 0.f, l1 = 0.f;
        float oa[16][4];
#pragma unroll
        for (int i = 0; i < 16; i++)
#pragma unroll
            for (int j = 0; j < 4; j++) oa[i][j] = 0.f;

        for (int jb = 0; jb <= ib; jb++) {
            const int buf = jb & 1;
            const uint32_t kbase = sb + (buf ? FKH1 : FKH0);
            const uint32_t vbase = sb + (buf ? FVH1 : FVH0);
            const int* sid_sm = (const int*)(sm + (buf ? FSD1 : FSD0));

            CPWAIT0();
            __syncthreads();
            if (jb < ib) {
                if (buf) KVLOAD(jb + 1, FKH0, FVH0); else KVLOAD(jb + 1, FKH1, FVH1);
                CPCOMMIT();
                if (tid < 128) ((int*)(sm + (buf ? FSD0 : FSD1)))[tid] = sid[(jb + 1) * 128 + tid];
            }

            float s[16][4];
#pragma unroll
            for (int i = 0; i < 16; i++)
#pragma unroll
                for (int j = 0; j < 4; j++) s[i][j] = 0.f;

#pragma unroll
            for (int kk = 0; kk < 8; kk++) {
                uint32_t ah[4], al[4];
                ldsm4(ah, arh + kk * 32);
                ldsm4(al, arl + kk * 32);
#pragma unroll
                for (int ng = 0; ng < 8; ng++) {
                    uint32_t bh[4];
                    ldsm4(bh, kbase + (uint32_t)(ng * 16 + (lane & 15)) * 272
                                  + (uint32_t)(lane >> 4) * 16 + kk * 32);
#pragma unroll
                    for (int o = 0; o < 2; o++) {
                        uint32_t bf[2] = {bh[o], bh[o + 2]};
                        mma16816(s[ng * 2 + o], ah, bf);
                        mma16816(s[ng * 2 + o], al, bf);
                    }
                }
            }

            const int cloc = (lane & 3) * 2;
#pragma unroll
            for (int nt = 0; nt < 16; nt++) {
                const int c0l = nt * 8 + cloc;
                const int sc0 = sid_sm[c0l], sc1 = sid_sm[c0l + 1];
                const int c0gl = jb * 128 + c0l;
                s[nt][0] = (sc0 == sid0 && c0gl <= r0g)         ? s[nt][0] * SCALE : -1e30f;
                s[nt][1] = (sc1 == sid0 && c0gl + 1 <= r0g)     ? s[nt][1] * SCALE : -1e30f;
                s[nt][2] = (sc0 == sid1 && c0gl <= r0g + 8)     ? s[nt][2] * SCALE : -1e30f;
                s[nt][3] = (sc1 == sid1 && c0gl + 1 <= r0g + 8) ? s[nt][3] * SCALE : -1e30f;
            }

            float tm0 = -1e30f, tm1 = -1e30f;
#pragma unroll
            for (int nt = 0; nt < 16; nt++) {
                tm0 = fmaxf(tm0, fmaxf(s[nt][0], s[nt][1]));
                tm1 = fmaxf(tm1, fmaxf(s[nt][2], s[nt][3]));
            }
            tm0 = fmaxf(tm0, __shfl_xor_sync(~0u, tm0, 1));
            tm0 = fmaxf(tm0, __shfl_xor_sync(~0u, tm0, 2));
            tm1 = fmaxf(tm1, __shfl_xor_sync(~0u, tm1, 1));
            tm1 = fmaxf(tm1, __shfl_xor_sync(~0u, tm1, 2));
            const float nm0 = fmaxf(m0, tm0), nm1 = fmaxf(m1, tm1);
            const float cf0 = __expf(m0 - nm0), cf1 = __expf(m1 - nm1);
            m0 = nm0; m1 = nm1;
            float rs0 = 0.f, rs1 = 0.f;
#pragma unroll
            for (int nt = 0; nt < 16; nt++) {
                float p0 = (s[nt][0] > -1e29f) ? __expf(s[nt][0] - nm0) : 0.f;
                float p1 = (s[nt][1] > -1e29f) ? __expf(s[nt][1] - nm0) : 0.f;
                float p2 = (s[nt][2] > -1e29f) ? __expf(s[nt][2] - nm1) : 0.f;
                float p3 = (s[nt][3] > -1e29f) ? __expf(s[nt][3] - nm1) : 0.f;
                s[nt][0] = p0; s[nt][1] = p1; s[nt][2] = p2; s[nt][3] = p3;
                rs0 += p0 + p1; rs1 += p2 + p3;
            }
            l0 = l0 * cf0 + rs0;
            l1 = l1 * cf1 + rs1;
#pragma unroll
            for (int nt = 0; nt < 16; nt++) {
                oa[nt][0] *= cf0; oa[nt][1] *= cf0;
                oa[nt][2] *= cf1; oa[nt][3] *= cf1;
            }

#pragma unroll
            for (int kp = 0; kp < 8; kp++) {
                uint32_t pah[4];
                {
                    const float* t0 = s[kp * 2];
                    const float* t1 = s[kp * 2 + 1];
                    pah[0] = pack_h2(t0[0], t0[1]);
                    pah[1] = pack_h2(t0[2], t0[3]);
                    pah[2] = pack_h2(t1[0], t1[1]);
                    pah[3] = pack_h2(t1[2], t1[3]);
                }
                const uint32_t vk = vbase + (uint32_t)(kp * 16) * 272 + vrow_off;
#pragma unroll
                for (int ng = 0; ng < 8; ng++) {
                    uint32_t vb[4];
                    ldsm4t(vb, vk + ng * 32);
#pragma unroll
                    for (int o = 0; o < 2; o++) {
                        uint32_t bf[2] = {vb[o * 2], vb[o * 2 + 1]};
                        mma16816(oa[ng * 2 + o], pah, bf);
                    }
                }
            }
        }

        l0 += __shfl_xor_sync(~0u, l0, 1); l0 += __shfl_xor_sync(~0u, l0, 2);
        l1 += __shfl_xor_sync(~0u, l1, 1); l1 += __shfl_xor_sync(~0u, l1, 2);
        const float i0 = 1.f / l0, i1 = 1.f / l1;
        const int cbase = h * D + (lane & 3) * 2;
        uint32_t* oh0 = (uint32_t*)aoh + (((size_t)r0g * 2048 + cbase) >> 1);
        uint32_t* oh1 = (uint32_t*)aoh + (((size_t)(r0g + 8) * 2048 + cbase) >> 1);
#pragma unroll
        for (int nt = 0; nt < 16; nt++) {
            oh0[nt * 4] = pack_h2(oa[nt][0] * i0, oa[nt][1] * i0);
            oh1[nt * 4] = pack_h2(oa[nt][2] * i1, oa[nt][3] * i1);
        }
    }
}

// ================= elementwise kernels =================
__global__ void split16_v4(const float4* __restrict__ in, uint2* __restrict__ out, int n4) {
    const int stride = gridDim.x * blockDim.x;
    for (int i = blockIdx.x * blockDim.x + threadIdx.x; i < n4; i += stride) {
        float4 a = in[i];
        out[i] = make_uint2(pack_h2(a.x, a.y), pack_h2(a.z, a.w));
    }
}

__global__ void interleave16_v4(const float4* __restrict__ wg, const float4* __restrict__ wu,
                                uint2* __restrict__ dst) {
    const int n4 = INTERM * (HID / 4);
    const int stride = gridDim.x * blockDim.x;
    for (int i = blockIdx.x * blockDim.x + threadIdx.x; i < n4; i += stride) {
        int j = i >> 9, cq = i & 511;
        float4 a = wg[i];
        float4 b = wu[i];
        dst[(size_t)(2 * j) * 512 + cq] = make_uint2(pack_h2(a.x, a.y), pack_h2(a.z, a.w));
        dst[(size_t)(2 * j + 1) * 512 + cq] = make_uint2(pack_h2(b.x, b.y), pack_h2(b.z, b.w));
    }
}

__global__ void rmsnorm16(const float* __restrict__ x, const float* __restrict__ w,
                          __half* __restrict__ oh, int dim) {
    int row = blockIdx.x;
    const float* xr = x + (size_t)row * dim;
    float ss = 0.f;
    for (int i = threadIdx.x * 4; i < dim; i += blockDim.x * 4) {
        float4 v = *(const float4*)(xr + i);
        ss += v.x * v.x + v.y * v.y + v.z * v.z + v.w * v.w;
    }
    __shared__ float red[32];
    for (int o = 16; o; o >>= 1) ss += __shfl_xor_sync(~0u, ss, o);
    if ((threadIdx.x & 31) == 0) red[threadIdx.x >> 5] = ss;
    __syncthreads();
    if (threadIdx.x < 32) {
        float v = (threadIdx.x < (blockDim.x >> 5)) ? red[threadIdx.x] : 0.f;
        for (int o = 16; o; o >>= 1) v += __shfl_xor_sync(~0u, v, o);
        if (threadIdx.x == 0) red[0] = v;
    }
    __syncthreads();
    float inv = rsqrtf(red[0] / (float)dim + 1e-6f);
    for (int i = threadIdx.x * 4; i < dim; i += blockDim.x * 4) {
        float4 v = *(const float4*)(xr + i);
        float4 ww = *(const float4*)(w + i);
        uint2 o2;
        o2.x = pack_h2(v.x * inv * ww.x, v.y * inv * ww.y);
        o2.y = pack_h2(v.z * inv * ww.z, v.w * inv * ww.w);
        *(uint2*)((uint32_t*)oh + (((size_t)row * dim + i) >> 1)) = o2;
    }
}

__global__ void rope_split(const float* __restrict__ qkv, const int* __restrict__ pos,
                           __half* __restrict__ qh, __half* __restrict__ ql,
                           __half* __restrict__ kh, __half* __restrict__ vh) {
    int idx = blockIdx.x * blockDim.x + threadIdx.x;
    if (idx >= SEQ * 32 * 64) return;
    int j = idx & 63;
    int slot = (idx >> 6) & 31;
    int srow = idx >> 11;
    const float* base = qkv + (size_t)srow * 4096 + slot * 128;
    float x0 = base[j], x1 = base[j + 64];
    float y0, y1;
    if (slot < 24) {
        float p = (float)pos[srow];
        float invf = __expf(-(float)j * (logf(10000.f) / 64.f));
        float ang = p * invf;
        float c = cosf(ang), sn = sinf(ang);
        y0 = x0 * c - x1 * sn;
        y1 = x1 * c + x0 * sn;
    } else { y0 = x0; y1 = x1; }
    if (slot < 16) {
        size_t o = (size_t)srow * 2048 + slot * 128;
        __half h0 = __float2half_rn(y0), h1 = __float2half_rn(y1);
        qh[o + j] = h0;      qh[o + j + 64] = h1;
        ql[o + j] = __float2half_rn(y0 - __half2float(h0));
        ql[o + j + 64] = __float2half_rn(y1 - __half2float(h1));
    } else if (slot < 24) {
        size_t o = (size_t)srow * 1024 + (slot - 16) * 128;
        kh[o + j] = __float2half_rn(y0);
        kh[o + j + 64] = __float2half_rn(y1);
    } else {
        size_t o = (size_t)srow * 1024 + (slot - 24) * 128;
        vh[o + j] = __float2half_rn(y0);
        vh[o + j + 64] = __float2half_rn(y1);
    }
}

extern "C" void kernel_launch(void* const* d_in, const int* in_sizes, int n_in,
                              void* d_out, int out_size) {
    const float* hs  = (const float*)d_in[0];
    const int*   sid = (const int*)d_in[1];
    const int*   pos = (const int*)d_in[2];
    const float* ln1 = (const float*)d_in[3];
    const float* wq  = (const float*)d_in[4];
    const float* wk  = (const float*)d_in[5];
    const float* wv  = (const float*)d_in[6];
    const float* wo  = (const float*)d_in[7];
    const float* ln2 = (const float*)d_in[8];
    const float* wg  = (const float*)d_in[9];
    const float* wu  = (const float*)d_in[10];
    const float* wd  = (const float*)d_in[11];
    float* out = (float*)d_out;

    float *qkv, *hb;
    __half *xnh, *qh, *ql, *kh, *vh, *aoh, *yh, *gh;
    __half *wqkvh, *woh, *wguh, *wdh;
    cudaGetSymbolAddress((void**)&qkv, g_qkv);
    cudaGetSymbolAddress((void**)&hb,  g_hb);
    cudaGetSymbolAddress((void**)&xnh, g_xnh);
    cudaGetSymbolAddress((void**)&qh,  g_qh);  cudaGetSymbolAddress((void**)&ql, g_ql);
    cudaGetSymbolAddress((void**)&kh,  g_kh);  cudaGetSymbolAddress((void**)&vh, g_vh);
    cudaGetSymbolAddress((void**)&aoh, g_aoh);
    cudaGetSymbolAddress((void**)&yh,  g_yh);
    cudaGetSymbolAddress((void**)&gh,  g_gh);
    cudaGetSymbolAddress((void**)&wqkvh, g_wqkvh);
    cudaGetSymbolAddress((void**)&woh,   g_woh);
    cudaGetSymbolAddress((void**)&wguh,  g_wguh);
    cudaGetSymbolAddress((void**)&wdh,   g_wdh);

    cudaFuncSetAttribute(hmma_gemm<false>, cudaFuncAttributeMaxDynamicSharedMemorySize, HM_SMEM);
    cudaFuncSetAttribute(hmma_gemm<true>,  cudaFuncAttributeMaxDynamicSharedMemorySize, HM_SMEM);
    cudaFuncSetAttribute(flash_attn, cudaFuncAttributeMaxDynamicSharedMemorySize, FL_SMEM);

    // side stream for weight splits not needed until o-proj / MLP
    static cudaStream_t s1 = nullptr;
    static cudaEvent_t ev_fork = nullptr, ev_join = nullptr;
    if (!s1) {
        cudaStreamCreateWithFlags(&s1, cudaStreamNonBlocking);
        cudaEventCreateWithFlags(&ev_fork, cudaEventDisableTiming);
        cudaEventCreateWithFlags(&ev_join, cudaEventDisableTiming);
    }

    // fork: s1 branches off the (captured) main stream
    cudaEventRecord(ev_fork, 0);
    cudaStreamWaitEvent(s1, ev_fork, 0);
    split16_v4<<<1184, 256, 0, s1>>>((const float4*)wo, (uint2*)woh, 2048 * 2048 / 4);
    interleave16_v4<<<2368, 256, 0, s1>>>((const float4*)wg, (const float4*)wu, (uint2*)wguh);
    split16_v4<<<2368, 256, 0, s1>>>((const float4*)wd, (uint2*)wdh, 2048 * 8192 / 4);
    cudaEventRecord(ev_join, s1);

    // main stream: qkv path
    split16_v4<<<1184, 256>>>((const float4*)wq, (uint2*)wqkvh, 2048 * 2048 / 4);
    split16_v4<<<1184, 256>>>((const float4*)wk, (uint2*)(wqkvh + 2048 * 2048), 1024 * 2048 / 4);
    split16_v4<<<1184, 256>>>((const float4*)wv, (uint2*)(wqkvh + 3072 * 2048), 1024 * 2048 / 4);
    rmsnorm16<<<SEQ, 256>>>(hs, ln1, xnh, HID);
    hmma_gemm<false><<<dim3(32, 16), 256, HM_SMEM>>>(xnh, wqkvh, qkv, 4096, nullptr, 1.f, HID, nullptr);
    rope_split<<<(SEQ * 32 * 64 + 255) / 256, 256>>>(qkv, pos, qh, ql, kh, vh);
    flash_attn<<<128, 256, FL_SMEM>>>(qh, ql, kh, vh, sid, aoh);

    // join: o-proj and MLP need s1's weights
    cudaStreamWaitEvent(0, ev_join, 0);
    hmma_gemm<false><<<dim3(16, 16), 256, HM_SMEM>>>(aoh, woh, hb, HID, hs, 1.f, 2048, nullptr);
    rmsnorm16<<<SEQ, 256>>>(hb, ln2, yh, HID);
    hmma_gemm<true><<<dim3(128, 16), 256, HM_SMEM>>>(yh, wguh, nullptr, 16384, nullptr, 1.f, HID, gh);
    hmma_gemm<false><<<dim3(16, 16), 256, HM_SMEM>>>(gh, wdh, out, HID, hb, 1.f, INTERM, nullptr);
}

// round 14
// speedup vs baseline: 1.0315x; 1.0204x over previous
#include <cuda_runtime.h>
#include <cuda_fp16.h>
#include <cstdint>
#include <math.h>

#define SEQ 2048
#define H 16
#define KVH 8
#define D 128
#define HID 2048
#define INTERM 8192
#define SCALE 0.08838834764831845f

// ---------------- scratch (device globals) ----------------
__device__ float  g_qkv[SEQ * 4096];
__device__ __half g_xnh[SEQ * HID];
__device__ __half g_qh[SEQ * 2048];
__device__ __half g_kh[SEQ * 1024], g_vh[SEQ * 1024];
__device__ __half g_aoh[SEQ * 2048];
__device__ float  g_hb[SEQ * HID];
__device__ __half g_yh[SEQ * HID];
__device__ __half g_gh[SEQ * INTERM];
__device__ __half g_wqkvh[4096 * 2048];
__device__ __half g_woh[2048 * 2048];
__device__ __half g_wguh[16384 * 2048];
__device__ __half g_wdh[2048 * 8192];

// ================= helpers =================
__device__ __forceinline__ uint32_t smem_to_u32(const void* p) {
    uint32_t a;
    asm("{ .reg .u64 t; cvta.to.shared.u64 t, %1; cvt.u32.u64 %0, t; }" : "=r"(a) : "l"(p));
    return a;
}
__device__ __forceinline__ uint32_t pack_h2(float a, float b) {
    __half2 h = __floats2half2_rn(a, b);
    return *reinterpret_cast<uint32_t*>(&h);
}
__device__ __forceinline__ void ldsm4(uint32_t* r, uint32_t addr) {
    asm volatile("ldmatrix.sync.aligned.m8n8.x4.shared.b16 {%0,%1,%2,%3}, [%4];"
                 : "=r"(r[0]), "=r"(r[1]), "=r"(r[2]), "=r"(r[3]) : "r"(addr));
}
__device__ __forceinline__ void ldsm4t(uint32_t* r, uint32_t addr) {
    asm volatile("ldmatrix.sync.aligned.m8n8.x4.trans.shared.b16 {%0,%1,%2,%3}, [%4];"
                 : "=r"(r[0]), "=r"(r[1]), "=r"(r[2]), "=r"(r[3]) : "r"(addr));
}
__device__ __forceinline__ void mma16816(float* c, const uint32_t* a, const uint32_t* b) {
    asm volatile(
        "mma.sync.aligned.m16n8k16.row.col.f32.f16.f16.f32 "
        "{%0,%1,%2,%3}, {%4,%5,%6,%7}, {%8,%9}, {%0,%1,%2,%3};"
        : "+f"(c[0]), "+f"(c[1]), "+f"(c[2]), "+f"(c[3])
        : "r"(a[0]), "r"(a[1]), "r"(a[2]), "r"(a[3]), "r"(b[0]), "r"(b[1]));
}
#define CP16(dst, src) \
    asm volatile("cp.async.cg.shared.global [%0], [%1], 16;" :: "r"(dst), "l"(src) : "memory")
#define CPCOMMIT() asm volatile("cp.async.commit_group;" ::: "memory")
#define CPWAIT0()  asm volatile("cp.async.wait_group 0;" ::: "memory")
#define CPWAIT1()  asm volatile("cp.async.wait_group 1;" ::: "memory")
#define CPWAIT2()  asm volatile("cp.async.wait_group 2;" ::: "memory")

// ================= hmma_gemm (R11 best-measured version) =================
#define STG 20480
#define HM_SMEM (4 * STG)

template <bool SILU>
__global__ void __launch_bounds__(256, 2) hmma_gemm(
    const __half* __restrict__ Ah, const __half* __restrict__ Bh,
    float* __restrict__ C, int ldc,
    const float* __restrict__ add, float alpha, int K,
    __half* __restrict__ HC) {
    extern __shared__ char sm[];
    const int tid = threadIdx.x;
    const int lane = tid & 31, wid = tid >> 5;
    const int wm = wid >> 1, wn = wid & 1;
    const int m0 = blockIdx.y * 128, n0 = blockIdx.x * 128;

    const uint32_t sb = smem_to_u32(sm);
    const uint32_t aoff = sb + (uint32_t)(wm * 32 + (lane & 15)) * 80 + (uint32_t)(lane >> 4) * 16;
    const uint32_t boff = sb + 10240 + (uint32_t)(wn * 64 + (lane & 15)) * 80 + (uint32_t)(lane >> 4) * 16;

    const int r = tid >> 1;
    const uint32_t sA = (uint32_t)r * 80 + (uint32_t)(tid & 1) * 32;
    const char* agh = (const char*)(Ah + (size_t)(m0 + r) * K) + (tid & 1) * 32;
    const char* bgh = (const char*)(Bh + (size_t)(n0 + r) * K) + (tid & 1) * 32;

#define PREFETCH(st, kt) do { \
    const uint32_t _d = sb + (uint32_t)(st) * STG + sA; \
    const size_t _o = (size_t)(kt) * 64; \
    CP16(_d,          agh + _o); CP16(_d + 16,          agh + _o + 16); \
    CP16(_d + 10240,  bgh + _o); CP16(_d + 10240 + 16,  bgh + _o + 16); \
    CPCOMMIT(); \
} while (0)

    float acc[2][8][4];
#pragma unroll
    for (int i = 0; i < 2; i++)
#pragma unroll
        for (int j = 0; j < 8; j++)
#pragma unroll
            for (int l = 0; l < 4; l++) acc[i][j][l] = 0.f;

    const int nk = K >> 5;
    PREFETCH(0, 0);
    PREFETCH(1, 1);
    PREFETCH(2, 2);

    for (int kt = 0; kt < nk; kt++) {
        const int ahead = nk - kt - 1;
        if (ahead >= 2)      CPWAIT2();
        else if (ahead == 1) CPWAIT1();
        else                 CPWAIT0();
        __syncthreads();
        if (kt + 3 < nk) PREFETCH((kt + 3) & 3, kt + 3);
        const uint32_t so = (uint32_t)(kt & 3) * STG;

#pragma unroll
        for (int kk = 0; kk < 2; kk++) {
            uint32_t ah[2][4], bh[4][4];
#pragma unroll
            for (int mt = 0; mt < 2; mt++)
                ldsm4(ah[mt], aoff + so + mt * 1280 + kk * 32);
#pragma unroll
            for (int g = 0; g < 4; g++) ldsm4(bh[g], boff + so + g * 1280 + kk * 32);
#pragma unroll
            for (int mt = 0; mt < 2; mt++)
#pragma unroll
                for (int nt = 0; nt < 8; nt++) {
                    const int g = nt >> 1, o = nt & 1;
                    uint32_t bf[2] = {bh[g][o], bh[g][o + 2]};
                    mma16816(acc[mt][nt], ah[mt], bf);
                }
        }
    }
    __syncthreads();

    const int rb = m0 + wm * 32 + (lane >> 2);
    const int cb = n0 + wn * 64 + (lane & 3) * 2;
    if (SILU) {
#pragma unroll
        for (int mt = 0; mt < 2; mt++)
#pragma unroll
            for (int nt = 0; nt < 8; nt++) {
                const int r0 = rb + mt * 16;
                const int oc = (cb + nt * 8) >> 1;
                float g0 = acc[mt][nt][0], u0 = acc[mt][nt][1];
                float g1 = acc[mt][nt][2], u1 = acc[mt][nt][3];
                float v0 = g0 / (1.f + __expf(-g0)) * u0;
                float v1 = g1 / (1.f + __expf(-g1)) * u1;
                HC[(size_t)r0 * (ldc >> 1) + oc] = __float2half_rn(v0);
                HC[(size_t)(r0 + 8) * (ldc >> 1) + oc] = __float2half_rn(v1);
            }
    } else {
#pragma unroll
        for (int mt = 0; mt < 2; mt++)
#pragma unroll
            for (int nt = 0; nt < 8; nt++) {
                const int r0 = rb + mt * 16;
                const int c = cb + nt * 8;
                float2 v0 = make_float2(alpha * acc[mt][nt][0], alpha * acc[mt][nt][1]);
                float2 v1 = make_float2(alpha * acc[mt][nt][2], alpha * acc[mt][nt][3]);
                if (add) {
                    float2 d0 = *(const float2*)(add + (size_t)r0 * ldc + c);
                    float2 d1 = *(const float2*)(add + (size_t)(r0 + 8) * ldc + c);
                    v0.x += d0.x; v0.y += d0.y; v1.x += d1.x; v1.y += d1.y;
                }
                *(float2*)(C + (size_t)r0 * ldc + c) = v0;
                *(float2*)(C + (size_t)(r0 + 8) * ldc + c) = v1;
            }
    }
}

// ================= flash attention, LPT-paired, single-fp16 Q/K/V/P =================
#define FQH 0
#define FKH0 34816
#define FKH1 69632
#define FVH0 104448
#define FVH1 139264
#define FSD0 174080
#define FSD1 174592
#define FL_SMEM 175104

__global__ void __launch_bounds__(256, 1) flash_attn(
    const __half* __restrict__ qh,
    const __half* __restrict__ kh, const __half* __restrict__ vh,
    const int* __restrict__ sid, __half* __restrict__ aoh) {
    extern __shared__ char sm[];
    const int z = blockIdx.x;
    const int p = z >> 4;
    const int h = z & 15;
    const int kvh = h >> 1;
    const int tid = threadIdx.x, lane = tid & 31, w = tid >> 5;
    const uint32_t sb = smem_to_u32(sm);

    const int r = tid >> 1;
    const uint32_t half_off = (uint32_t)(tid & 1) * 128;
    const int hcol = (tid & 1) * 64;
    const uint32_t dstrow = sb + (uint32_t)r * 272 + half_off;

#define KVLOAD(jb, kdst, vdst) do { \
    const __half* _ks = kh + (size_t)((jb) * 128 + r) * 1024 + kvh * 128 + hcol; \
    const __half* _vs = vh + (size_t)((jb) * 128 + r) * 1024 + kvh * 128 + hcol; \
    _Pragma("unroll") \
    for (int x = 0; x < 8; x++) { \
        CP16(dstrow + (kdst) + x * 16, (const char*)_ks + x * 16); \
        CP16(dstrow + (vdst) + x * 16, (const char*)_vs + x * 16); \
    } \
} while (0)

    const int vg = lane >> 3, vlr = lane & 7;
    const uint32_t vrow_off = (uint32_t)((vg & 1) * 8 + vlr) * 272 + (uint32_t)(vg >> 1) * 16;
    const uint32_t arh = sb + FQH + (uint32_t)(w * 16 + (lane & 15)) * 272 + (uint32_t)(lane >> 4) * 16;

    for (int half = 0; half < 2; half++) {
        const int ib = half == 0 ? 15 - p : p;
        __syncthreads();   // previous half's smem reads fully done

        // prologue: Q + KV(0) + sid(0)
        {
            const __half* qs = qh + (size_t)(ib * 128 + r) * 2048 + h * 128 + hcol;
#pragma unroll
            for (int x = 0; x < 8; x++)
                CP16(dstrow + FQH + x * 16, (const char*)qs + x * 16);
            KVLOAD(0, FKH0, FVH0);
            CPCOMMIT();
            if (tid < 128) ((int*)(sm + FSD0))[tid] = sid[tid];
        }

        const int r0g = ib * 128 + w * 16 + (lane >> 2);
        const int sid0 = sid[r0g], sid1 = sid[r0g + 8];

        float m0 = -1e30f, m1 = -1e30f, l0 = 0.f, l1 = 0.f;
        float oa[16][4];
#pragma unroll
        for (int i = 0; i < 16; i++)
#pragma unroll
            for (int j = 0; j < 4; j++) oa[i][j] = 0.f;

        for (int jb = 0; jb <= ib; jb++) {
            const int buf = jb & 1;
            const uint32_t kbase = sb + (buf ? FKH1 : FKH0);
            const uint32_t vbase = sb + (buf ? FVH1 : FVH0);
            const int* sid_sm = (const int*)(sm + (buf ? FSD1 : FSD0));

            CPWAIT0();
            __syncthreads();
            if (jb < ib) {
                if (buf) KVLOAD(jb + 1, FKH0, FVH0); else KVLOAD(jb + 1, FKH1, FVH1);
                CPCOMMIT();
                if (tid < 128) ((int*)(sm + (buf ? FSD0 : FSD1)))[tid] = sid[(jb + 1) * 128 + tid];
            }

            float s[16][4];
#pragma unroll
            for (int i = 0; i < 16; i++)
#pragma unroll
                for (int j = 0; j < 4; j++) s[i][j] = 0.f;

#pragma unroll
            for (int kk = 0; kk < 8; kk++) {
                uint32_t ah[4];
                ldsm4(ah, arh + kk * 32);
#pragma unroll
                for (int ng = 0; ng < 8; ng++) {
                    uint32_t bh[4];
                    ldsm4(bh, kbase + (uint32_t)(ng * 16 + (lane & 15)) * 272
                                  + (uint32_t)(lane >> 4) * 16 + kk * 32);
#pragma unroll
                    for (int o = 0; o < 2; o++) {
                        uint32_t bf[2] = {bh[o], bh[o + 2]};
                        mma16816(s[ng * 2 + o], ah, bf);
                    }
                }
            }

            const int cloc = (lane & 3) * 2;
#pragma unroll
            for (int nt = 0; nt < 16; nt++) {
                const int c0l = nt * 8 + cloc;
                const int sc0 = sid_sm[c0l], sc1 = sid_sm[c0l + 1];
                const int c0gl = jb * 128 + c0l;
                s[nt][0] = (sc0 == sid0 && c0gl <= r0g)         ? s[nt][0] * SCALE : -1e30f;
                s[nt][1] = (sc1 == sid0 && c0gl + 1 <= r0g)     ? s[nt][1] * SCALE : -1e30f;
                s[nt][2] = (sc0 == sid1 && c0gl <= r0g + 8)     ? s[nt][2] * SCALE : -1e30f;
                s[nt][3] = (sc1 == sid1 && c0gl + 1 <= r0g + 8) ? s[nt][3] * SCALE : -1e30f;
            }

            float tm0 = -1e30f, tm1 = -1e30f;
#pragma unroll
            for (int nt = 0; nt < 16; nt++) {
                tm0 = fmaxf(tm0, fmaxf(s[nt][0], s[nt][1]));
                tm1 = fmaxf(tm1, fmaxf(s[nt][2], s[nt][3]));
            }
            tm0 = fmaxf(tm0, __shfl_xor_sync(~0u, tm0, 1));
            tm0 = fmaxf(tm0, __shfl_xor_sync(~0u, tm0, 2));
            tm1 = fmaxf(tm1, __shfl_xor_sync(~0u, tm1, 1));
            tm1 = fmaxf(tm1, __shfl_xor_sync(~0u, tm1, 2));
            const float nm0 = fmaxf(m0, tm0), nm1 = fmaxf(m1, tm1);
            const float cf0 = __expf(m0 - nm0), cf1 = __expf(m1 - nm1);
            m0 = nm0; m1 = nm1;
            float rs0 = 0.f, rs1 = 0.f;
#pragma unroll
            for (int nt = 0; nt < 16; nt++) {
                float p0 = (s[nt][0] > -1e29f) ? __expf(s[nt][0] - nm0) : 0.f;
                float p1 = (s[nt][1] > -1e29f) ? __expf(s[nt][1] - nm0) : 0.f;
                float p2 = (s[nt][2] > -1e29f) ? __expf(s[nt][2] - nm1) : 0.f;
                float p3 = (s[nt][3] > -1e29f) ? __expf(s[nt][3] - nm1) : 0.f;
                s[nt][0] = p0; s[nt][1] = p1; s[nt][2] = p2; s[nt][3] = p3;
                rs0 += p0 + p1; rs1 += p2 + p3;
            }
            l0 = l0 * cf0 + rs0;
            l1 = l1 * cf1 + rs1;
#pragma unroll
            for (int nt = 0; nt < 16; nt++) {
                oa[nt][0] *= cf0; oa[nt][1] *= cf0;
                oa[nt][2] *= cf1; oa[nt][3] *= cf1;
            }

#pragma unroll
            for (int kp = 0; kp < 8; kp++) {
                uint32_t pah[4];
                {
                    const float* t0 = s[kp * 2];
                    const float* t1 = s[kp * 2 + 1];
                    pah[0] = pack_h2(t0[0], t0[1]);
                    pah[1] = pack_h2(t0[2], t0[3]);
                    pah[2] = pack_h2(t1[0], t1[1]);
                    pah[3] = pack_h2(t1[2], t1[3]);
                }
                const uint32_t vk = vbase + (uint32_t)(kp * 16) * 272 + vrow_off;
#pragma unroll
                for (int ng = 0; ng < 8; ng++) {
                    uint32_t vb[4];
                    ldsm4t(vb, vk + ng * 32);
#pragma unroll
                    for (int o = 0; o < 2; o++) {
                        uint32_t bf[2] = {vb[o * 2], vb[o * 2 + 1]};
                        mma16816(oa[ng * 2 + o], pah, bf);
                    }
                }
            }
        }

        l0 += __shfl_xor_sync(~0u, l0, 1); l0 += __shfl_xor_sync(~0u, l0, 2);
        l1 += __shfl_xor_sync(~0u, l1, 1); l1 += __shfl_xor_sync(~0u, l1, 2);
        const float i0 = 1.f / l0, i1 = 1.f / l1;
        const int cbase = h * D + (lane & 3) * 2;
        uint32_t* oh0 = (uint32_t*)aoh + (((size_t)r0g * 2048 + cbase) >> 1);
        uint32_t* oh1 = (uint32_t*)aoh + (((size_t)(r0g + 8) * 2048 + cbase) >> 1);
#pragma unroll
        for (int nt = 0; nt < 16; nt++) {
            oh0[nt * 4] = pack_h2(oa[nt][0] * i0, oa[nt][1] * i0);
            oh1[nt * 4] = pack_h2(oa[nt][2] * i1, oa[nt][3] * i1);
        }
    }
}

// ================= elementwise kernels =================
__global__ void split16_v4(const float4* __restrict__ in, uint2* __restrict__ out, int n4) {
    const int stride = gridDim.x * blockDim.x;
    for (int i = blockIdx.x * blockDim.x + threadIdx.x; i < n4; i += stride) {
        float4 a = in[i];
        out[i] = make_uint2(pack_h2(a.x, a.y), pack_h2(a.z, a.w));
    }
}

// merged wq|wk|wv -> wqkvh, one launch
__global__ void qkv_split_v4(const float4* __restrict__ wq, const float4* __restrict__ wk,
                             const float4* __restrict__ wv, uint2* __restrict__ dst) {
    const int nq = 2048 * 2048 / 4, nk = 1024 * 2048 / 4;
    const int n4 = 4096 * 2048 / 4;
    const int stride = gridDim.x * blockDim.x;
    for (int i = blockIdx.x * blockDim.x + threadIdx.x; i < n4; i += stride) {
        float4 a;
        if (i < nq)           a = wq[i];
        else if (i < nq + nk) a = wk[i - nq];
        else                  a = wv[i - nq - nk];
        dst[i] = make_uint2(pack_h2(a.x, a.y), pack_h2(a.z, a.w));
    }
}

__global__ void interleave16_v4(const float4* __restrict__ wg, const float4* __restrict__ wu,
                                uint2* __restrict__ dst) {
    const int n4 = INTERM * (HID / 4);
    const int stride = gridDim.x * blockDim.x;
    for (int i = blockIdx.x * blockDim.x + threadIdx.x; i < n4; i += stride) {
        int j = i >> 9, cq = i & 511;
        float4 a = wg[i];
        float4 b = wu[i];
        dst[(size_t)(2 * j) * 512 + cq] = make_uint2(pack_h2(a.x, a.y), pack_h2(a.z, a.w));
        dst[(size_t)(2 * j + 1) * 512 + cq] = make_uint2(pack_h2(b.x, b.y), pack_h2(b.z, b.w));
    }
}

__global__ void rmsnorm16(const float* __restrict__ x, const float* __restrict__ w,
                          __half* __restrict__ oh, int dim) {
    int row = blockIdx.x;
    const float* xr = x + (size_t)row * dim;
    float ss = 0.f;
    for (int i = threadIdx.x * 4; i < dim; i += blockDim.x * 4) {
        float4 v = *(const float4*)(xr + i);
        ss += v.x * v.x + v.y * v.y + v.z * v.z + v.w * v.w;
    }
    __shared__ float red[32];
    for (int o = 16; o; o >>= 1) ss += __shfl_xor_sync(~0u, ss, o);
    if ((threadIdx.x & 31) == 0) red[threadIdx.x >> 5] = ss;
    __syncthreads();
    if (threadIdx.x < 32) {
        float v = (threadIdx.x < (blockDim.x >> 5)) ? red[threadIdx.x] : 0.f;
        for (int o = 16; o; o >>= 1) v += __shfl_xor_sync(~0u, v, o);
        if (threadIdx.x == 0) red[0] = v;
    }
    __syncthreads();
    float inv = rsqrtf(red[0] / (float)dim + 1e-6f);
    for (int i = threadIdx.x * 4; i < dim; i += blockDim.x * 4) {
        float4 v = *(const float4*)(xr + i);
        float4 ww = *(const float4*)(w + i);
        uint2 o2;
        o2.x = pack_h2(v.x * inv * ww.x, v.y * inv * ww.y);
        o2.y = pack_h2(v.z * inv * ww.z, v.w * inv * ww.w);
        *(uint2*)((uint32_t*)oh + (((size_t)row * dim + i) >> 1)) = o2;
    }
}

__global__ void rope_split(const float* __restrict__ qkv, const int* __restrict__ pos,
                           __half* __restrict__ qh,
                           __half* __restrict__ kh, __half* __restrict__ vh) {
    int idx = blockIdx.x * blockDim.x + threadIdx.x;
    if (idx >= SEQ * 32 * 64) return;
    int j = idx & 63;
    int slot = (idx >> 6) & 31;
    int srow = idx >> 11;
    const float* base = qkv + (size_t)srow * 4096 + slot * 128;
    float x0 = base[j], x1 = base[j + 64];
    float y0, y1;
    if (slot < 24) {
        float p = (float)pos[srow];
        float invf = __expf(-(float)j * (logf(10000.f) / 64.f));
        float ang = p * invf;
        float c = cosf(ang), sn = sinf(ang);
        y0 = x0 * c - x1 * sn;
        y1 = x1 * c + x0 * sn;
    } else { y0 = x0; y1 = x1; }
    if (slot < 16) {
        size_t o = (size_t)srow * 2048 + slot * 128;
        qh[o + j] = __float2half_rn(y0);
        qh[o + j + 64] = __float2half_rn(y1);
    } else if (slot < 24) {
        size_t o = (size_t)srow * 1024 + (slot - 16) * 128;
        kh[o + j] = __float2half_rn(y0);
        kh[o + j + 64] = __float2half_rn(y1);
    } else {
        size_t o = (size_t)srow * 1024 + (slot - 24) * 128;
        vh[o + j] = __float2half_rn(y0);
        vh[o + j + 64] = __float2half_rn(y1);
    }
}

extern "C" void kernel_launch(void* const* d_in, const int* in_sizes, int n_in,
                              void* d_out, int out_size) {
    const float* hs  = (const float*)d_in[0];
    const int*   sid = (const int*)d_in[1];
    const int*   pos = (const int*)d_in[2];
    const float* ln1 = (const float*)d_in[3];
    const float* wq  = (const float*)d_in[4];
    const float* wk  = (const float*)d_in[5];
    const float* wv  = (const float*)d_in[6];
    const float* wo  = (const float*)d_in[7];
    const float* ln2 = (const float*)d_in[8];
    const float* wg  = (const float*)d_in[9];
    const float* wu  = (const float*)d_in[10];
    const float* wd  = (const float*)d_in[11];
    float* out = (float*)d_out;

    float *qkv, *hb;
    __half *xnh, *qh, *kh, *vh, *aoh, *yh, *gh;
    __half *wqkvh, *woh, *wguh, *wdh;
    cudaGetSymbolAddress((void**)&qkv, g_qkv);
    cudaGetSymbolAddress((void**)&hb,  g_hb);
    cudaGetSymbolAddress((void**)&xnh, g_xnh);
    cudaGetSymbolAddress((void**)&qh,  g_qh);
    cudaGetSymbolAddress((void**)&kh,  g_kh);  cudaGetSymbolAddress((void**)&vh, g_vh);
    cudaGetSymbolAddress((void**)&aoh, g_aoh);
    cudaGetSymbolAddress((void**)&yh,  g_yh);
    cudaGetSymbolAddress((void**)&gh,  g_gh);
    cudaGetSymbolAddress((void**)&wqkvh, g_wqkvh);
    cudaGetSymbolAddress((void**)&woh,   g_woh);
    cudaGetSymbolAddress((void**)&wguh,  g_wguh);
    cudaGetSymbolAddress((void**)&wdh,   g_wdh);

    cudaFuncSetAttribute(hmma_gemm<false>, cudaFuncAttributeMaxDynamicSharedMemorySize, HM_SMEM);
    cudaFuncSetAttribute(hmma_gemm<true>,  cudaFuncAttributeMaxDynamicSharedMemorySize, HM_SMEM);
    cudaFuncSetAttribute(flash_attn, cudaFuncAttributeMaxDynamicSharedMemorySize, FL_SMEM);

    static cudaStream_t s1 = nullptr;
    static cudaEvent_t ev_fork = nullptr, ev_join = nullptr;
    if (!s1) {
        cudaStreamCreateWithFlags(&s1, cudaStreamNonBlocking);
        cudaEventCreateWithFlags(&ev_fork, cudaEventDisableTiming);
        cudaEventCreateWithFlags(&ev_join, cudaEventDisableTiming);
    }

    // fork: wo/wgu/wd splits overlap with qkv path
    cudaEventRecord(ev_fork, 0);
    cudaStreamWaitEvent(s1, ev_fork, 0);
    split16_v4<<<1184, 256, 0, s1>>>((const float4*)wo, (uint2*)woh, 2048 * 2048 / 4);
    interleave16_v4<<<2368, 256, 0, s1>>>((const float4*)wg, (const float4*)wu, (uint2*)wguh);
    split16_v4<<<2368, 256, 0, s1>>>((const float4*)wd, (uint2*)wdh, 2048 * 8192 / 4);
    cudaEventRecord(ev_join, s1);

    // main stream
    qkv_split_v4<<<2368, 256>>>((const float4*)wq, (const float4*)wk, (const float4*)wv, (uint2*)wqkvh);
    rmsnorm16<<<SEQ, 256>>>(hs, ln1, xnh, HID);
    hmma_gemm<false><<<dim3(32, 16), 256, HM_SMEM>>>(xnh, wqkvh, qkv, 4096, nullptr, 1.f, HID, nullptr);
    rope_split<<<(SEQ * 32 * 64 + 255) / 256, 256>>>(qkv, pos, qh, kh, vh);
    flash_attn<<<128, 256, FL_SMEM>>>(qh, kh, vh, sid, aoh);

    cudaStreamWaitEvent(0, ev_join, 0);
    hmma_gemm<false><<<dim3(16, 16), 256, HM_SMEM>>>(aoh, woh, hb, HID, hs, 1.f, 2048, nullptr);
    rmsnorm16<<<SEQ, 256>>>(hb, ln2, yh, HID);
    hmma_gemm<true><<<dim3(128, 16), 256, HM_SMEM>>>(yh, wguh, nullptr, 16384, nullptr, 1.f, HID, gh);
    hmma_gemm<false><<<dim3(16, 16), 256, HM_SMEM>>>(gh, wdh, out, HID, hb, 1.f, INTERM, nullptr);
}